// round 2
// baseline (speedup 1.0000x reference)
#include <cuda_runtime.h>

#define DIM 256
#define RPB 16          // rows (batch elements) per CTA
#define NTH 256
#define KMAX 64

typedef unsigned long long u64;

__device__ __forceinline__ u64 pack2(float x) {
    u64 r; asm("mov.b64 %0, {%1, %1};" : "=l"(r) : "f"(x)); return r;
}
__device__ __forceinline__ void ffma2(u64 &d, u64 a, u64 b) {
    asm("fma.rn.f32x2 %0, %1, %2, %0;" : "+l"(d) : "l"(a), "l"(b));
}
__device__ __forceinline__ float2 unpack2(u64 v) {
    float2 f; asm("mov.b64 {%0, %1}, %2;" : "=f"(f.x), "=f"(f.y) : "l"(v)); return f;
}

__global__ __launch_bounds__(NTH)
void easyrec_fused(const int* __restrict__ nodes_u,
                   const int* __restrict__ nodes_v,
                   const int* __restrict__ neighbors,
                   const int* __restrict__ neighbor_counts,
                   const float* __restrict__ u2e,
                   const float* __restrict__ v2e,
                   const float* __restrict__ W,     // [D, 2D] row-major
                   const float* __restrict__ bvec,  // [D]
                   float* __restrict__ out,
                   int B)
{
    __shared__ float svt[DIM][RPB];     // TRANSPOSED v tile: svt[j][r], 16 KB
    __shared__ int   snb[RPB][KMAX];    // neighbor indices, 4 KB
    __shared__ int   scnt[RPB];
    __shared__ int   su[RPB];
    __shared__ float sred[RPB][8];

    const int t    = threadIdx.x;
    const int row0 = blockIdx.x * RPB;

    // ---- Phase A: gather v tile (coalesced read, transposed smem write) ----
    #pragma unroll
    for (int r = 0; r < RPB; r++) {
        int b  = row0 + r; if (b >= B) b = B - 1;
        int vi = nodes_v[b];
        svt[t][r] = v2e[(size_t)vi * DIM + t];
    }
    for (int i = t; i < RPB * KMAX; i += NTH) {
        int r = i >> 6, k = i & 63;
        int b = row0 + r; if (b >= B) b = B - 1;
        snb[r][k] = neighbors[(size_t)b * KMAX + k];
    }
    if (t < RPB) {
        int b = row0 + t; if (b >= B) b = B - 1;
        scnt[t] = neighbor_counts[b];
        su[t]   = nodes_u[b];
    }
    __syncthreads();

    // ---- Phase B: g[r] = v[r] @ W, packed f32x2 over row pairs.
    // Thread t owns output columns t (g1) and t+256 (g2) for all 16 rows.
    // acc1[p] = (g1[2p][t], g1[2p+1][t]) packed; same for acc2 at col t+256.
    u64 acc1[RPB / 2], acc2[RPB / 2];
    #pragma unroll
    for (int p = 0; p < RPB / 2; p++) { acc1[p] = 0ull; acc2[p] = 0ull; }

    const float* Wc = W + t;
    float wa0 = Wc[0],           wb0 = Wc[DIM];
    float wa1 = Wc[2 * DIM],     wb1 = Wc[3 * DIM];

    #pragma unroll 1
    for (int j = 0; j < DIM; j += 2) {
        u64 pa0 = pack2(wa0), pb0 = pack2(wb0);
        u64 pa1 = pack2(wa1), pb1 = pack2(wb1);
        if (j + 2 < DIM) {
            const float* w = Wc + (size_t)(j + 2) * (2 * DIM);
            wa0 = w[0];       wb0 = w[DIM];
            wa1 = w[2 * DIM]; wb1 = w[3 * DIM];
        }
        #pragma unroll
        for (int q = 0; q < 4; q++) {
            // rows 4q..4q+3 at depth j and j+1: two LDS.128 broadcasts, no packs
            ulonglong2 v0 = *reinterpret_cast<const ulonglong2*>(&svt[j    ][4 * q]);
            ulonglong2 v1 = *reinterpret_cast<const ulonglong2*>(&svt[j + 1][4 * q]);
            ffma2(acc1[2 * q    ], v0.x, pa0);
            ffma2(acc1[2 * q + 1], v0.y, pa0);
            ffma2(acc2[2 * q    ], v0.x, pb0);
            ffma2(acc2[2 * q + 1], v0.y, pb0);
            ffma2(acc1[2 * q    ], v1.x, pa1);
            ffma2(acc1[2 * q + 1], v1.y, pa1);
            ffma2(acc2[2 * q    ], v1.x, pb1);
            ffma2(acc2[2 * q + 1], v1.y, pb1);
        }
    }

    const float bt = bvec[t];

    // ---- Phase C: neighbor gather + score. Fully static acc indexing. ----
    auto do_row = [&](int r, float g1, float g2) {
        const int   cnt   = scnt[r];
        const float selfv = u2e[(size_t)su[r] * DIM + t];   // coalesced
        const float vrt   = svt[t][r];
        float partial;
        if (cnt > 0) {
            float n0 = 0.f, n1 = 0.f, n2 = 0.f, n3 = 0.f;
            int k = 0;
            #pragma unroll 1
            for (; k + 4 <= cnt; k += 4) {
                n0 += u2e[(size_t)snb[r][k + 0] * DIM + t];
                n1 += u2e[(size_t)snb[r][k + 1] * DIM + t];
                n2 += u2e[(size_t)snb[r][k + 2] * DIM + t];
                n3 += u2e[(size_t)snb[r][k + 3] * DIM + t];
            }
            #pragma unroll 1
            for (; k < cnt; k++) n0 += u2e[(size_t)snb[r][k] * DIM + t];
            const float nsum = (n0 + n1) + (n2 + n3);
            partial = selfv * g1 + nsum * (1.f / (float)cnt) * g2 + bt * vrt;
        } else {
            partial = selfv * vrt;      // no-neighbor fallback: self . v
        }
        #pragma unroll
        for (int o = 16; o; o >>= 1)
            partial += __shfl_down_sync(0xffffffffu, partial, o);
        if ((t & 31) == 0) sred[r][t >> 5] = partial;
    };

    #pragma unroll
    for (int p = 0; p < RPB / 2; p++) {
        float2 g1 = unpack2(acc1[p]);
        float2 g2 = unpack2(acc2[p]);
        do_row(2 * p,     g1.x, g2.x);
        do_row(2 * p + 1, g1.y, g2.y);
    }
    __syncthreads();

    if (t < RPB) {
        float s = 0.f;
        #pragma unroll
        for (int w = 0; w < 8; w++) s += sred[t][w];
        if (row0 + t < B) out[row0 + t] = s;
    }
}

extern "C" void kernel_launch(void* const* d_in, const int* in_sizes, int n_in,
                              void* d_out, int out_size)
{
    const int*   nodes_u         = (const int*)  d_in[0];
    const int*   nodes_v         = (const int*)  d_in[1];
    const int*   neighbors       = (const int*)  d_in[2];
    const int*   neighbor_counts = (const int*)  d_in[3];
    const float* u2e             = (const float*)d_in[4];
    const float* v2e             = (const float*)d_in[5];
    const float* W               = (const float*)d_in[6];
    const float* bvec            = (const float*)d_in[7];
    float*       out             = (float*)d_out;

    const int B = in_sizes[0];
    const int grid = (B + RPB - 1) / RPB;
    easyrec_fused<<<grid, NTH>>>(nodes_u, nodes_v, neighbors, neighbor_counts,
                                 u2e, v2e, W, bvec, out, B);
}